// round 5
// baseline (speedup 1.0000x reference)
#include <cuda_runtime.h>

#define NCOLS  8192
#define TARGET 7680
#define NWIN   513
#define NT     256
#define KPT    32

__device__ __forceinline__ unsigned f2key(float x) {
    unsigned u = __float_as_uint(x);
    return (u & 0x80000000u) ? ~u : (u | 0x80000000u);
}
__device__ __forceinline__ float key2f(unsigned k) {
    unsigned u = (k & 0x80000000u) ? (k ^ 0x80000000u) : ~k;
    return __uint_as_float(u);
}

__device__ __forceinline__ void cas(unsigned& a, unsigned& b, bool up) {
    unsigned x = a, y = b;
    unsigned mn = min(x, y), mx = max(x, y);
    a = up ? mn : mx;
    b = up ? mx : mn;
}

__device__ __forceinline__ void sort8(unsigned v[8], bool up) {
    cas(v[0], v[4], up); cas(v[1], v[5], up); cas(v[2], v[6], up); cas(v[3], v[7], up);
    cas(v[0], v[2], up); cas(v[1], v[3], up); cas(v[4], v[6], up); cas(v[5], v[7], up);
    cas(v[0], v[1], up); cas(v[2], v[3], up); cas(v[4], v[5], up); cas(v[6], v[7], up);
}

__device__ __forceinline__ void shfl_pass(unsigned v[8], int delta, bool up, int ts) {
    bool keepmin = (up == ((ts & delta) == 0));
    if (keepmin) {
        #pragma unroll
        for (int e = 0; e < 8; ++e)
            v[e] = min(v[e], __shfl_xor_sync(0xffffffffu, v[e], delta));
    } else {
        #pragma unroll
        for (int e = 0; e < 8; ++e)
            v[e] = max(v[e], __shfl_xor_sync(0xffffffffu, v[e], delta));
    }
}

__device__ __forceinline__ void smem_pass(unsigned v[8], int delta, bool up,
                                          int t, int ts, unsigned* scratch) {
    __syncthreads();
    #pragma unroll
    for (int e = 0; e < 8; ++e) scratch[t * 8 + e] = v[e];
    __syncthreads();
    bool keepmin = (up == ((ts & delta) == 0));
    int pt = t ^ delta;
    if (keepmin) {
        #pragma unroll
        for (int e = 0; e < 8; ++e) v[e] = min(v[e], scratch[pt * 8 + e]);
    } else {
        #pragma unroll
        for (int e = 0; e < 8; ++e) v[e] = max(v[e], scratch[pt * 8 + e]);
    }
}

// ---- exact fallback helpers (block-uniform; never taken for N(0,1) data) ----
__device__ unsigned block_count(const float4* x4, unsigned K, bool ge,
                                unsigned* s_red, int tid) {
    if (tid == 0) *s_red = 0;
    __syncthreads();
    unsigned c = 0;
    for (int i = tid; i < NCOLS / 4; i += NT) {
        float4 w = x4[i];
        unsigned k0 = f2key(w.x), k1 = f2key(w.y), k2 = f2key(w.z), k3 = f2key(w.w);
        if (ge) c += (k0 >= K) + (k1 >= K) + (k2 >= K) + (k3 >= K);
        else    c += (k0 <= K) + (k1 <= K) + (k2 <= K) + (k3 <= K);
    }
    #pragma unroll
    for (int off = 16; off; off >>= 1) c += __shfl_down_sync(0xffffffffu, c, off);
    if ((tid & 31) == 0) atomicAdd(s_red, c);
    __syncthreads();
    unsigned r = *s_red;
    __syncthreads();
    return r;
}

__device__ unsigned gather_side(const float4* x4, unsigned T, int side,
                                unsigned* seg, unsigned* s_c, int tid) {
    if (tid == 0) *s_c = 0;
    __syncthreads();
    const int lane = tid & 31;
    for (int i = tid; i < NCOLS / 4; i += NT) {
        float4 w = x4[i];
        unsigned kk[4] = { f2key(w.x), f2key(w.y), f2key(w.z), f2key(w.w) };
        #pragma unroll
        for (int q = 0; q < 4; ++q) {
            bool take = side ? (kk[q] > T) : (kk[q] < T);
            unsigned m = __ballot_sync(0xffffffffu, take);
            unsigned base = 0;
            if (lane == 0 && m) base = atomicAdd(s_c, (unsigned)__popc(m));
            base = __shfl_sync(0xffffffffu, base, 0);
            if (take) {
                unsigned p = base + __popc(m & ((1u << lane) - 1u));
                if (p < 1024) seg[p] = kk[q];
            }
        }
    }
    __syncthreads();
    unsigned r = *s_c;
    __syncthreads();
    return r;
}

__global__ __launch_bounds__(NT, 5)
void recall_window_kernel(const float* __restrict__ x,
                          float* __restrict__ out, int rows)
{
    __shared__ unsigned skey[NCOLS];       // 32 KB staged keys
    __shared__ unsigned scratch[2048];     // 8 KB: two 1024 sort segments
    __shared__ unsigned wsum[8];
    __shared__ unsigned s_c;
    __shared__ unsigned long long s_best;

    const int t    = threadIdx.x;
    const int lane = t & 31;
    const int wid  = t >> 5;
    const int ts   = t & 127;
    const int row  = blockIdx.x;
    const float4* x4 = reinterpret_cast<const float4*>(x + (size_t)row * NCOLS);
    uint4* sk4 = reinterpret_cast<uint4*>(skey);

    const unsigned kTlo = f2key(-1.31f);
    const unsigned kThi = f2key( 1.31f);

    // ---- phase 1: load, convert, stage to smem, count tail takes ----
    unsigned clo = 0, chi = 0;
    #pragma unroll
    for (int e4 = 0; e4 < KPT / 4; ++e4) {
        float4 w = x4[e4 * NT + t];
        uint4 kk;
        kk.x = f2key(w.x); kk.y = f2key(w.y);
        kk.z = f2key(w.z); kk.w = f2key(w.w);
        sk4[e4 * NT + t] = kk;
        clo += (kk.x < kTlo) + (kk.y < kTlo) + (kk.z < kTlo) + (kk.w < kTlo);
        chi += (kk.x > kThi) + (kk.y > kThi) + (kk.z > kThi) + (kk.w > kThi);
    }

    // ---- phase 2: block exclusive scan of packed (clo | chi<<16) ----
    unsigned packed = clo | (chi << 16);
    unsigned incl = packed;
    #pragma unroll
    for (int off = 1; off < 32; off <<= 1) {
        unsigned v = __shfl_up_sync(0xffffffffu, incl, off);
        if (lane >= off) incl += v;
    }
    if (lane == 31) wsum[wid] = incl;
    __syncthreads();
    unsigned wbase = 0, tot = 0;
    #pragma unroll
    for (int w = 0; w < 8; ++w) {
        unsigned s = wsum[w];
        if (w < wid) wbase += s;
        tot += s;
    }
    unsigned excl   = wbase + incl - packed;
    unsigned baselo = excl & 0xFFFFu, basehi = excl >> 16;
    unsigned totlo  = tot  & 0xFFFFu, tothi  = tot  >> 16;

    const bool ok_lo = (totlo >= 513u && totlo <= 1024u);
    const bool ok_hi = (tothi >= 513u && tothi <= 1024u);

    // ---- phase 3: scatter from staged smem keys (no ballots/atomics) ----
    if (ok_lo && ok_hi) {
        unsigned plo = baselo, phi = basehi;
        #pragma unroll
        for (int e4 = 0; e4 < KPT / 4; ++e4) {
            uint4 kk = sk4[e4 * NT + t];
            unsigned ka[4] = { kk.x, kk.y, kk.z, kk.w };
            #pragma unroll
            for (int q = 0; q < 4; ++q) {
                unsigned k = ka[q];
                if (k < kTlo)      scratch[plo++] = k;
                else if (k > kThi) scratch[1024 + phi++] = k;
            }
        }
    }
    __syncthreads();

    unsigned c0 = totlo, c1 = tothi;
    if (!ok_lo) {                                   // exact fallback (cold)
        unsigned Kcut;
        if (block_count(x4, 0u, false, &s_c, t) >= 513u) {
            Kcut = 0u;
        } else {
            unsigned X = 0;
            for (int b = 31; b >= 0; --b) {
                unsigned X2 = X | (1u << b);
                if (block_count(x4, X2, false, &s_c, t) < 513u) X = X2;
            }
            Kcut = X + 1u;
        }
        c0 = gather_side(x4, Kcut, 0, scratch, &s_c, t);
        for (int i = (int)c0 + t; i < 513; i += NT) scratch[i] = Kcut;
        c0 = 513u;
    }
    if (!ok_hi) {
        unsigned Y = 0;
        for (int b = 31; b >= 0; --b) {
            unsigned Y2 = Y | (1u << b);
            if (block_count(x4, Y2, true, &s_c, t) >= 513u) Y = Y2;
        }
        c1 = gather_side(x4, Y, 1, scratch + 1024, &s_c, t);
        for (int i = (int)c1 + t; i < 513; i += NT) scratch[1024 + i] = Y;
        c1 = 513u;
    }
    for (int i = (int)c0 + t; i < 1024; i += NT) scratch[i]        = 0xFFFFFFFFu;
    for (int i = (int)c1 + t; i < 1024; i += NT) scratch[1024 + i] = 0u;
    if (t == 0) s_best = ~0ull;
    __syncthreads();

    // ---- phase 4: register-blocked bitonic, two independent 1024 sorts ----
    unsigned v[8];
    #pragma unroll
    for (int e = 0; e < 8; ++e) v[e] = scratch[t * 8 + e];

    cas(v[0], v[1], true);  cas(v[2], v[3], false);
    cas(v[4], v[5], true);  cas(v[6], v[7], false);
    cas(v[0], v[2], true);  cas(v[1], v[3], true);
    cas(v[4], v[6], false); cas(v[5], v[7], false);
    cas(v[0], v[1], true);  cas(v[2], v[3], true);
    cas(v[4], v[5], false); cas(v[6], v[7], false);
    sort8(v, (ts & 1) == 0);

    #pragma unroll
    for (int kk = 16; kk <= 1024; kk <<= 1) {
        bool up = ((ts & (kk >> 3)) == 0);
        #pragma unroll
        for (int j = kk >> 1; j >= 8; j >>= 1) {
            int delta = j >> 3;
            if (delta >= 32) smem_pass(v, delta, up, t, ts, scratch);
            else             shfl_pass(v, delta, up, ts);
        }
        sort8(v, up);
    }

    __syncthreads();
    #pragma unroll
    for (int e = 0; e < 8; ++e) scratch[t * 8 + e] = v[e];
    __syncthreads();

    // ---- phase 5: lengths + first-index argmin ----
    unsigned long long best = ~0ull;
    for (int i = t; i < NWIN; i += NT) {
        float len = key2f(scratch[1024 + 511 + i]) - key2f(scratch[i]);
        unsigned long long p =
            ((unsigned long long)__float_as_uint(len) << 32) | (unsigned)i;
        if (p < best) best = p;
    }
    #pragma unroll
    for (int off = 16; off; off >>= 1) {
        unsigned long long o = __shfl_down_sync(0xffffffffu, best, off);
        if (o < best) best = o;
    }
    if (lane == 0) atomicMin(&s_best, best);
    __syncthreads();

    if (t == 0) {
        int idx = (int)(unsigned)(s_best & 0xffffffffu);
        out[row]        = key2f(scratch[idx]);
        out[rows + row] = key2f(scratch[1024 + 511 + idx]);
    }
}

extern "C" void kernel_launch(void* const* d_in, const int* in_sizes, int n_in,
                              void* d_out, int out_size) {
    const float* x = (const float*)d_in[0];
    float* out = (float*)d_out;
    int rows = in_sizes[0] / NCOLS;   // 4096
    recall_window_kernel<<<rows, NT>>>(x, out, rows);
}

// round 6
// speedup vs baseline: 3.0408x; 3.0408x over previous
#include <cuda_runtime.h>

#define NCOLS  8192
#define TARGET 7680
#define NWIN   513
#define NT     256
#define KPT    32

__device__ __forceinline__ unsigned f2key(float x) {
    unsigned u = __float_as_uint(x);
    return (u & 0x80000000u) ? ~u : (u | 0x80000000u);
}
__device__ __forceinline__ float key2f(unsigned k) {
    unsigned u = (k & 0x80000000u) ? (k ^ 0x80000000u) : ~k;
    return __uint_as_float(u);
}

__device__ __forceinline__ void cas(unsigned& a, unsigned& b, bool up) {
    unsigned x = a, y = b;
    unsigned mn = min(x, y), mx = max(x, y);
    a = up ? mn : mx;
    b = up ? mx : mn;
}

__device__ __forceinline__ void sort8(unsigned v[8], bool up) {
    cas(v[0], v[4], up); cas(v[1], v[5], up); cas(v[2], v[6], up); cas(v[3], v[7], up);
    cas(v[0], v[2], up); cas(v[1], v[3], up); cas(v[4], v[6], up); cas(v[5], v[7], up);
    cas(v[0], v[1], up); cas(v[2], v[3], up); cas(v[4], v[5], up); cas(v[6], v[7], up);
}

// BRANCHLESS: keepmin varies within the warp for delta<32; a divergent branch
// around a full-mask shfl serializes both sides (R5 regression). SEL instead.
__device__ __forceinline__ void shfl_pass(unsigned v[8], int delta, bool up, int ts) {
    bool keepmin = (up == ((ts & delta) == 0));
    #pragma unroll
    for (int e = 0; e < 8; ++e) {
        unsigned o  = __shfl_xor_sync(0xffffffffu, v[e], delta);
        unsigned mn = min(v[e], o), mx = max(v[e], o);
        v[e] = keepmin ? mn : mx;
    }
}

// delta >= 32 here: keepmin is warp-uniform, branch is free and kills 8 SELs.
__device__ __forceinline__ void smem_pass(unsigned v[8], int delta, bool up,
                                          int t, int ts, unsigned* scratch) {
    __syncthreads();
    #pragma unroll
    for (int e = 0; e < 8; ++e) scratch[t * 8 + e] = v[e];
    __syncthreads();
    bool keepmin = (up == ((ts & delta) == 0));
    int pt = t ^ delta;
    if (keepmin) {
        #pragma unroll
        for (int e = 0; e < 8; ++e) v[e] = min(v[e], scratch[pt * 8 + e]);
    } else {
        #pragma unroll
        for (int e = 0; e < 8; ++e) v[e] = max(v[e], scratch[pt * 8 + e]);
    }
}

// ---- exact fallback helpers (block-uniform; never taken for N(0,1) data) ----
__device__ unsigned block_count(const float4* x4, unsigned K, bool ge,
                                unsigned* s_red, int tid) {
    if (tid == 0) *s_red = 0;
    __syncthreads();
    unsigned c = 0;
    for (int i = tid; i < NCOLS / 4; i += NT) {
        float4 w = x4[i];
        unsigned k0 = f2key(w.x), k1 = f2key(w.y), k2 = f2key(w.z), k3 = f2key(w.w);
        if (ge) c += (k0 >= K) + (k1 >= K) + (k2 >= K) + (k3 >= K);
        else    c += (k0 <= K) + (k1 <= K) + (k2 <= K) + (k3 <= K);
    }
    #pragma unroll
    for (int off = 16; off; off >>= 1) c += __shfl_down_sync(0xffffffffu, c, off);
    if ((tid & 31) == 0) atomicAdd(s_red, c);
    __syncthreads();
    unsigned r = *s_red;
    __syncthreads();
    return r;
}

__device__ unsigned gather_side(const float4* x4, unsigned T, int side,
                                unsigned* seg, unsigned* s_c, int tid) {
    if (tid == 0) *s_c = 0;
    __syncthreads();
    const int lane = tid & 31;
    for (int i = tid; i < NCOLS / 4; i += NT) {
        float4 w = x4[i];
        unsigned kk[4] = { f2key(w.x), f2key(w.y), f2key(w.z), f2key(w.w) };
        #pragma unroll
        for (int q = 0; q < 4; ++q) {
            bool take = side ? (kk[q] > T) : (kk[q] < T);
            unsigned m = __ballot_sync(0xffffffffu, take);
            unsigned base = 0;
            if (lane == 0 && m) base = atomicAdd(s_c, (unsigned)__popc(m));
            base = __shfl_sync(0xffffffffu, base, 0);
            if (take) {
                unsigned p = base + __popc(m & ((1u << lane) - 1u));
                if (p < 1024) seg[p] = kk[q];
            }
        }
    }
    __syncthreads();
    unsigned r = *s_c;
    __syncthreads();
    return r;
}

__global__ __launch_bounds__(NT, 5)
void recall_window_kernel(const float* __restrict__ x,
                          float* __restrict__ out, int rows)
{
    __shared__ unsigned skey[NCOLS];       // 32 KB staged keys
    __shared__ unsigned scratch[2048];     // 8 KB: two 1024 sort segments
    __shared__ unsigned wsum[8];
    __shared__ unsigned s_c;
    __shared__ unsigned long long s_best;

    const int t    = threadIdx.x;
    const int lane = t & 31;
    const int wid  = t >> 5;
    const int ts   = t & 127;
    const int row  = blockIdx.x;
    const float4* x4 = reinterpret_cast<const float4*>(x + (size_t)row * NCOLS);
    uint4* sk4 = reinterpret_cast<uint4*>(skey);

    const unsigned kTlo = f2key(-1.31f);
    const unsigned kThi = f2key( 1.31f);

    // ---- phase 1: load, convert, stage to smem, count tail takes ----
    unsigned clo = 0, chi = 0;
    #pragma unroll
    for (int e4 = 0; e4 < KPT / 4; ++e4) {
        float4 w = x4[e4 * NT + t];
        uint4 kk;
        kk.x = f2key(w.x); kk.y = f2key(w.y);
        kk.z = f2key(w.z); kk.w = f2key(w.w);
        sk4[e4 * NT + t] = kk;
        clo += (kk.x < kTlo) + (kk.y < kTlo) + (kk.z < kTlo) + (kk.w < kTlo);
        chi += (kk.x > kThi) + (kk.y > kThi) + (kk.z > kThi) + (kk.w > kThi);
    }

    // ---- phase 2: block exclusive scan of packed (clo | chi<<16) ----
    unsigned packed = clo | (chi << 16);
    unsigned incl = packed;
    #pragma unroll
    for (int off = 1; off < 32; off <<= 1) {
        unsigned v = __shfl_up_sync(0xffffffffu, incl, off);
        if (lane >= off) incl += v;
    }
    if (lane == 31) wsum[wid] = incl;
    __syncthreads();
    unsigned wbase = 0, tot = 0;
    #pragma unroll
    for (int w = 0; w < 8; ++w) {
        unsigned s = wsum[w];
        if (w < wid) wbase += s;
        tot += s;
    }
    unsigned excl   = wbase + incl - packed;
    unsigned baselo = excl & 0xFFFFu, basehi = excl >> 16;
    unsigned totlo  = tot  & 0xFFFFu, tothi  = tot  >> 16;

    const bool ok_lo = (totlo >= 513u && totlo <= 1024u);
    const bool ok_hi = (tothi >= 513u && tothi <= 1024u);

    // ---- phase 3: scatter from staged smem keys (no ballots/atomics) ----
    if (ok_lo && ok_hi) {
        unsigned plo = baselo, phi = basehi;
        #pragma unroll
        for (int e4 = 0; e4 < KPT / 4; ++e4) {
            uint4 kk = sk4[e4 * NT + t];
            unsigned ka[4] = { kk.x, kk.y, kk.z, kk.w };
            #pragma unroll
            for (int q = 0; q < 4; ++q) {
                unsigned k = ka[q];
                if (k < kTlo)      scratch[plo++] = k;
                else if (k > kThi) scratch[1024 + phi++] = k;
            }
        }
    }
    __syncthreads();

    unsigned c0 = totlo, c1 = tothi;
    if (!ok_lo) {                                   // exact fallback (cold)
        unsigned Kcut;
        if (block_count(x4, 0u, false, &s_c, t) >= 513u) {
            Kcut = 0u;
        } else {
            unsigned X = 0;
            for (int b = 31; b >= 0; --b) {
                unsigned X2 = X | (1u << b);
                if (block_count(x4, X2, false, &s_c, t) < 513u) X = X2;
            }
            Kcut = X + 1u;
        }
        c0 = gather_side(x4, Kcut, 0, scratch, &s_c, t);
        for (int i = (int)c0 + t; i < 513; i += NT) scratch[i] = Kcut;
        c0 = 513u;
    }
    if (!ok_hi) {
        unsigned Y = 0;
        for (int b = 31; b >= 0; --b) {
            unsigned Y2 = Y | (1u << b);
            if (block_count(x4, Y2, true, &s_c, t) >= 513u) Y = Y2;
        }
        c1 = gather_side(x4, Y, 1, scratch + 1024, &s_c, t);
        for (int i = (int)c1 + t; i < 513; i += NT) scratch[1024 + i] = Y;
        c1 = 513u;
    }
    for (int i = (int)c0 + t; i < 1024; i += NT) scratch[i]        = 0xFFFFFFFFu;
    for (int i = (int)c1 + t; i < 1024; i += NT) scratch[1024 + i] = 0u;
    if (t == 0) s_best = ~0ull;
    __syncthreads();

    // ---- phase 4: register-blocked bitonic, two independent 1024 sorts ----
    unsigned v[8];
    #pragma unroll
    for (int e = 0; e < 8; ++e) v[e] = scratch[t * 8 + e];

    cas(v[0], v[1], true);  cas(v[2], v[3], false);
    cas(v[4], v[5], true);  cas(v[6], v[7], false);
    cas(v[0], v[2], true);  cas(v[1], v[3], true);
    cas(v[4], v[6], false); cas(v[5], v[7], false);
    cas(v[0], v[1], true);  cas(v[2], v[3], true);
    cas(v[4], v[5], false); cas(v[6], v[7], false);
    sort8(v, (ts & 1) == 0);

    #pragma unroll
    for (int kk = 16; kk <= 1024; kk <<= 1) {
        bool up = ((ts & (kk >> 3)) == 0);
        #pragma unroll
        for (int j = kk >> 1; j >= 8; j >>= 1) {
            int delta = j >> 3;
            if (delta >= 32) smem_pass(v, delta, up, t, ts, scratch);
            else             shfl_pass(v, delta, up, ts);
        }
        sort8(v, up);
    }

    __syncthreads();
    #pragma unroll
    for (int e = 0; e < 8; ++e) scratch[t * 8 + e] = v[e];
    __syncthreads();

    // ---- phase 5: lengths + first-index argmin ----
    unsigned long long best = ~0ull;
    for (int i = t; i < NWIN; i += NT) {
        float len = key2f(scratch[1024 + 511 + i]) - key2f(scratch[i]);
        unsigned long long p =
            ((unsigned long long)__float_as_uint(len) << 32) | (unsigned)i;
        if (p < best) best = p;
    }
    #pragma unroll
    for (int off = 16; off; off >>= 1) {
        unsigned long long o = __shfl_down_sync(0xffffffffu, best, off);
        if (o < best) best = o;
    }
    if (lane == 0) atomicMin(&s_best, best);
    __syncthreads();

    if (t == 0) {
        int idx = (int)(unsigned)(s_best & 0xffffffffu);
        out[row]        = key2f(scratch[idx]);
        out[rows + row] = key2f(scratch[1024 + 511 + idx]);
    }
}

extern "C" void kernel_launch(void* const* d_in, const int* in_sizes, int n_in,
                              void* d_out, int out_size) {
    const float* x = (const float*)d_in[0];
    float* out = (float*)d_out;
    int rows = in_sizes[0] / NCOLS;   // 4096
    recall_window_kernel<<<rows, NT>>>(x, out, rows);
}

// round 7
// speedup vs baseline: 3.1723x; 1.0432x over previous
#include <cuda_runtime.h>

#define NCOLS  8192
#define TARGET 7680
#define NWIN   513
#define NT     256
#define KPT    32

#define TLO (-1.31f)
#define THI ( 1.31f)

__device__ __forceinline__ unsigned f2key(float x) {
    unsigned u = __float_as_uint(x);
    return (u & 0x80000000u) ? ~u : (u | 0x80000000u);
}
__device__ __forceinline__ float key2f(unsigned k) {
    unsigned u = (k & 0x80000000u) ? (k ^ 0x80000000u) : ~k;
    return __uint_as_float(u);
}

__device__ __forceinline__ void cas(unsigned& a, unsigned& b, bool up) {
    unsigned x = a, y = b;
    unsigned mn = min(x, y), mx = max(x, y);
    a = up ? mn : mx;
    b = up ? mx : mn;
}

__device__ __forceinline__ void sort8(unsigned v[8], bool up) {
    cas(v[0], v[4], up); cas(v[1], v[5], up); cas(v[2], v[6], up); cas(v[3], v[7], up);
    cas(v[0], v[2], up); cas(v[1], v[3], up); cas(v[4], v[6], up); cas(v[5], v[7], up);
    cas(v[0], v[1], up); cas(v[2], v[3], up); cas(v[4], v[5], up); cas(v[6], v[7], up);
}

// BRANCHLESS: keepmin varies within the warp for delta<32 (R5 regression proof).
__device__ __forceinline__ void shfl_pass(unsigned v[8], int delta, bool up, int ts) {
    bool keepmin = (up == ((ts & delta) == 0));
    #pragma unroll
    for (int e = 0; e < 8; ++e) {
        unsigned o  = __shfl_xor_sync(0xffffffffu, v[e], delta);
        unsigned mn = min(v[e], o), mx = max(v[e], o);
        v[e] = keepmin ? mn : mx;
    }
}

// delta >= 32: keepmin warp-uniform, branch is free.
__device__ __forceinline__ void smem_pass(unsigned v[8], int delta, bool up,
                                          int t, int ts, unsigned* scratch) {
    __syncthreads();
    #pragma unroll
    for (int e = 0; e < 8; ++e) scratch[t * 8 + e] = v[e];
    __syncthreads();
    bool keepmin = (up == ((ts & delta) == 0));
    int pt = t ^ delta;
    if (keepmin) {
        #pragma unroll
        for (int e = 0; e < 8; ++e) v[e] = min(v[e], scratch[pt * 8 + e]);
    } else {
        #pragma unroll
        for (int e = 0; e < 8; ++e) v[e] = max(v[e], scratch[pt * 8 + e]);
    }
}

// ---- exact fallback helpers (f2key domain; block-uniform; cold) ----
__device__ unsigned block_count(const float4* x4, unsigned K, bool ge,
                                unsigned* s_red, int tid) {
    if (tid == 0) *s_red = 0;
    __syncthreads();
    unsigned c = 0;
    for (int i = tid; i < NCOLS / 4; i += NT) {
        float4 w = x4[i];
        unsigned k0 = f2key(w.x), k1 = f2key(w.y), k2 = f2key(w.z), k3 = f2key(w.w);
        if (ge) c += (k0 >= K) + (k1 >= K) + (k2 >= K) + (k3 >= K);
        else    c += (k0 <= K) + (k1 <= K) + (k2 <= K) + (k3 <= K);
    }
    #pragma unroll
    for (int off = 16; off; off >>= 1) c += __shfl_down_sync(0xffffffffu, c, off);
    if ((tid & 31) == 0) atomicAdd(s_red, c);
    __syncthreads();
    unsigned r = *s_red;
    __syncthreads();
    return r;
}

__device__ unsigned gather_side(const float4* x4, unsigned T, int side,
                                unsigned* seg, unsigned* s_c, int tid) {
    if (tid == 0) *s_c = 0;
    __syncthreads();
    const int lane = tid & 31;
    for (int i = tid; i < NCOLS / 4; i += NT) {
        float4 w = x4[i];
        unsigned kk[4] = { f2key(w.x), f2key(w.y), f2key(w.z), f2key(w.w) };
        #pragma unroll
        for (int q = 0; q < 4; ++q) {
            bool take = side ? (kk[q] > T) : (kk[q] < T);
            unsigned m = __ballot_sync(0xffffffffu, take);
            unsigned base = 0;
            if (lane == 0 && m) base = atomicAdd(s_c, (unsigned)__popc(m));
            base = __shfl_sync(0xffffffffu, base, 0);
            if (take) {
                unsigned p = base + __popc(m & ((1u << lane) - 1u));
                if (p < 1024) seg[p] = kk[q];
            }
        }
    }
    __syncthreads();
    unsigned r = *s_c;
    __syncthreads();
    return r;
}

__global__ __launch_bounds__(NT, 6)
void recall_window_kernel(const float* __restrict__ x,
                          float* __restrict__ out, int rows)
{
    __shared__ unsigned scratch[2048];     // two 1024 sort segments
    __shared__ unsigned wsum[8];
    __shared__ unsigned s_c;
    __shared__ unsigned long long s_best;

    const int t    = threadIdx.x;
    const int lane = t & 31;
    const int wid  = t >> 5;
    const int ts   = t & 127;
    const int row  = blockIdx.x;
    const float4* x4 = reinterpret_cast<const float4*>(x + (size_t)row * NCOLS);

    // ---- phase 1: load + count tail takes (float compares, no key transform) ----
    unsigned clo = 0, chi = 0;
    #pragma unroll
    for (int e4 = 0; e4 < KPT / 4; ++e4) {
        float4 w = x4[e4 * NT + t];
        clo += (w.x < TLO) + (w.y < TLO) + (w.z < TLO) + (w.w < TLO);
        chi += (w.x > THI) + (w.y > THI) + (w.z > THI) + (w.w > THI);
    }

    // ---- phase 2: block exclusive scan of packed (clo | chi<<16) ----
    unsigned packed = clo | (chi << 16);
    unsigned incl = packed;
    #pragma unroll
    for (int off = 1; off < 32; off <<= 1) {
        unsigned v = __shfl_up_sync(0xffffffffu, incl, off);
        if (lane >= off) incl += v;
    }
    if (lane == 31) wsum[wid] = incl;
    __syncthreads();
    unsigned wbase = 0, tot = 0;
    #pragma unroll
    for (int w = 0; w < 8; ++w) {
        unsigned s = wsum[w];
        if (w < wid) wbase += s;
        tot += s;
    }
    unsigned excl   = wbase + incl - packed;
    unsigned baselo = excl & 0xFFFFu, basehi = excl >> 16;
    unsigned totlo  = tot  & 0xFFFFu, tothi  = tot  >> 16;

    const bool ok_lo = (totlo >= 513u && totlo <= 1024u);
    const bool ok_hi = (tothi >= 513u && tothi <= 1024u);

    // ---- phase 3: re-read row (L1/L2-hot), scatter raw-domain keys ----
    // lo segment stores ~rawbits (negative floats: asc uint == asc float)
    // hi segment stores  rawbits (positive floats: asc uint == asc float)
    if (ok_lo && ok_hi) {
        unsigned plo = baselo, phi = basehi;
        #pragma unroll
        for (int e4 = 0; e4 < KPT / 4; ++e4) {
            float4 w = x4[e4 * NT + t];
            float fa[4] = { w.x, w.y, w.z, w.w };
            #pragma unroll
            for (int q = 0; q < 4; ++q) {
                float f = fa[q];
                if (f < TLO)      scratch[plo++] = ~__float_as_uint(f);
                else if (f > THI) scratch[1024 + phi++] = __float_as_uint(f);
            }
        }
    }
    __syncthreads();

    unsigned c0 = totlo, c1 = tothi;
    if (!ok_lo) {                                   // exact fallback (cold, f2key domain)
        unsigned Kcut;
        if (block_count(x4, 0u, false, &s_c, t) >= 513u) {
            Kcut = 0u;
        } else {
            unsigned X = 0;
            for (int b = 31; b >= 0; --b) {
                unsigned X2 = X | (1u << b);
                if (block_count(x4, X2, false, &s_c, t) < 513u) X = X2;
            }
            Kcut = X + 1u;
        }
        c0 = gather_side(x4, Kcut, 0, scratch, &s_c, t);
        for (int i = (int)c0 + t; i < 513; i += NT) scratch[i] = Kcut;
        c0 = 513u;
    }
    if (!ok_hi) {
        unsigned Y = 0;
        for (int b = 31; b >= 0; --b) {
            unsigned Y2 = Y | (1u << b);
            if (block_count(x4, Y2, true, &s_c, t) >= 513u) Y = Y2;
        }
        c1 = gather_side(x4, Y, 1, scratch + 1024, &s_c, t);
        for (int i = (int)c1 + t; i < 513; i += NT) scratch[1024 + i] = Y;
        c1 = 513u;
    }
    // pads: lo-end with max keys, hi-front with 0 keys (valid in both domains)
    for (int i = (int)c0 + t; i < 1024; i += NT) scratch[i]        = 0xFFFFFFFFu;
    for (int i = (int)c1 + t; i < 1024; i += NT) scratch[1024 + i] = 0u;
    if (t == 0) s_best = ~0ull;
    __syncthreads();

    // ---- phase 4: register-blocked bitonic, two independent 1024 sorts ----
    unsigned v[8];
    #pragma unroll
    for (int e = 0; e < 8; ++e) v[e] = scratch[t * 8 + e];

    cas(v[0], v[1], true);  cas(v[2], v[3], false);
    cas(v[4], v[5], true);  cas(v[6], v[7], false);
    cas(v[0], v[2], true);  cas(v[1], v[3], true);
    cas(v[4], v[6], false); cas(v[5], v[7], false);
    cas(v[0], v[1], true);  cas(v[2], v[3], true);
    cas(v[4], v[5], false); cas(v[6], v[7], false);
    sort8(v, (ts & 1) == 0);

    #pragma unroll
    for (int kk = 16; kk <= 1024; kk <<= 1) {
        bool up = ((ts & (kk >> 3)) == 0);
        #pragma unroll
        for (int j = kk >> 1; j >= 8; j >>= 1) {
            int delta = j >> 3;
            if (delta >= 32) smem_pass(v, delta, up, t, ts, scratch);
            else             shfl_pass(v, delta, up, ts);
        }
        sort8(v, up);
    }

    __syncthreads();
    #pragma unroll
    for (int e = 0; e < 8; ++e) scratch[t * 8 + e] = v[e];
    __syncthreads();

    // ---- phase 5: lengths + first-index argmin (domain-aware decode) ----
    unsigned long long best = ~0ull;
    for (int i = t; i < NWIN; i += NT) {
        unsigned kl = scratch[i];
        unsigned kh = scratch[1024 + 511 + i];
        float fl = ok_lo ? __uint_as_float(~kl) : key2f(kl);
        float fh = ok_hi ? __uint_as_float(kh)  : key2f(kh);
        float len = fh - fl;
        unsigned long long p =
            ((unsigned long long)__float_as_uint(len) << 32) | (unsigned)i;
        if (p < best) best = p;
    }
    #pragma unroll
    for (int off = 16; off; off >>= 1) {
        unsigned long long o = __shfl_down_sync(0xffffffffu, best, off);
        if (o < best) best = o;
    }
    if (lane == 0) atomicMin(&s_best, best);
    __syncthreads();

    if (t == 0) {
        int idx = (int)(unsigned)(s_best & 0xffffffffu);
        unsigned kl = scratch[idx];
        unsigned kh = scratch[1024 + 511 + idx];
        out[row]        = ok_lo ? __uint_as_float(~kl) : key2f(kl);
        out[rows + row] = ok_hi ? __uint_as_float(kh)  : key2f(kh);
    }
}

extern "C" void kernel_launch(void* const* d_in, const int* in_sizes, int n_in,
                              void* d_out, int out_size) {
    const float* x = (const float*)d_in[0];
    float* out = (float*)d_out;
    int rows = in_sizes[0] / NCOLS;   // 4096
    recall_window_kernel<<<rows, NT>>>(x, out, rows);
}